// round 16
// baseline (speedup 1.0000x reference)
#include <cuda_runtime.h>
#include <cuda_fp16.h>
#include <cstdint>
#include <math.h>

#define EMBED 1024
#define HEADS 16
#define HDIM  64
#define BATCH 4
#define NQ    1024
#define NK    2048

// Scratch (static device memory) — fp16 intermediates only
__device__ __half g_Q[(size_t)BATCH * HEADS * NQ * HDIM];
__device__ __half g_K[(size_t)BATCH * HEADS * NK * HDIM];
__device__ __half g_V[(size_t)BATCH * HEADS * NK * HDIM];
__device__ __half g_A[(size_t)BATCH * NQ * EMBED];

__device__ __forceinline__ uint32_t smem_u32(const void* p) {
    return (uint32_t)__cvta_generic_to_shared(p);
}
__device__ __forceinline__ uint32_t packh2(float a, float b) {
    __half2 h = __floats2half2_rn(a, b);
    return *(uint32_t*)&h;
}

#define CP_ASYNC16(dst_u32, src_ptr) \
    asm volatile("cp.async.cg.shared.global [%0], [%1], 16;" :: "r"(dst_u32), "l"(src_ptr))
#define CP_COMMIT() asm volatile("cp.async.commit_group;")
#define CP_WAIT1()  asm volatile("cp.async.wait_group 1;")

__device__ __forceinline__ void mma_f16(float* c, const uint32_t* a, const uint32_t* b) {
    asm volatile(
        "mma.sync.aligned.m16n8k16.row.col.f32.f16.f16.f32 "
        "{%0,%1,%2,%3}, {%4,%5,%6,%7}, {%8,%9}, {%0,%1,%2,%3};"
        : "+f"(c[0]), "+f"(c[1]), "+f"(c[2]), "+f"(c[3])
        : "r"(a[0]), "r"(a[1]), "r"(a[2]), "r"(a[3]), "r"(b[0]), "r"(b[1]));
}
__device__ __forceinline__ void ldmx4(uint32_t& r0, uint32_t& r1, uint32_t& r2, uint32_t& r3,
                                      uint32_t addr) {
    asm volatile("ldmatrix.sync.aligned.m8n8.x4.shared.b16 {%0,%1,%2,%3}, [%4];"
                 : "=r"(r0), "=r"(r1), "=r"(r2), "=r"(r3) : "r"(addr));
}
__device__ __forceinline__ void ldmx4_trans(uint32_t& r0, uint32_t& r1, uint32_t& r2, uint32_t& r3,
                                            uint32_t addr) {
    asm volatile("ldmatrix.sync.aligned.m8n8.x4.trans.shared.b16 {%0,%1,%2,%3}, [%4];"
                 : "=r"(r0), "=r"(r1), "=r"(r2), "=r"(r3) : "r"(addr));
}

// ---------------------------------------------------------------------------
// GEMM pieces. Tile 128x128, BK=64, 8 warps (4m x 2n), 2-stage smem double
// buffer. Operand staging converts fp32 -> fp16 in-register (no prepass).
// ---------------------------------------------------------------------------
#define GSTR 72
#define GSTG (128 * GSTR)    // halves per tensor per stage

// stage one 128x64 fp32 tile -> fp16 smem (8 float4 per thread)
__device__ __forceinline__ void stage_f32tile(__half* dst, const float* __restrict__ src, int tid) {
#pragma unroll
    for (int j = 0; j < 8; j++) {
        int f = tid + j * 256;
        int r = f >> 4, c4 = f & 15;
        float4 v = *(const float4*)(src + (size_t)r * EMBED + c4 * 4);
        uint32_t h0 = packh2(v.x, v.y);
        uint32_t h1 = packh2(v.z, v.w);
        asm volatile("st.shared.v2.b32 [%0], {%1,%2};"
                     :: "r"(smem_u32(dst + r * GSTR + c4 * 4)), "r"(h0), "r"(h1) : "memory");
    }
}

// stage one 128x64 fp16 tile -> smem (4 uint4 per thread)
__device__ __forceinline__ void stage_f16tile(__half* dst, const __half* __restrict__ src, int tid) {
#pragma unroll
    for (int j = 0; j < 4; j++) {
        int f = tid + j * 256;
        int r = f >> 3, cc = f & 7;
        uint4 v = *(const uint4*)(src + (size_t)r * EMBED + cc * 8);
        asm volatile("st.shared.v4.b32 [%0], {%1,%2,%3,%4};"
                     :: "r"(smem_u32(dst + r * GSTR + cc * 8)),
                        "r"(v.x), "r"(v.y), "r"(v.z), "r"(v.w) : "memory");
    }
}

// one BK=64 compute iteration (ldmatrix + 64 HMMA per warp)
__device__ __forceinline__ void compute_iter(const __half* As, int wm, int wn,
                                             uint32_t aoff, uint32_t boff, float c[2][8][4]) {
    const uint32_t Abase = smem_u32(As) + aoff;
    const uint32_t Bbase = smem_u32(As + GSTG) + boff;
#pragma unroll
    for (int ks = 0; ks < 4; ks++) {
        uint32_t a[2][4];
#pragma unroll
        for (int mt = 0; mt < 2; mt++)
            ldmx4(a[mt][0], a[mt][1], a[mt][2], a[mt][3],
                  Abase + (uint32_t)(((wm * 32 + mt * 16) * GSTR + ks * 16) * 2));
#pragma unroll
        for (int ntp = 0; ntp < 4; ntp++) {
            uint32_t b0, b1, b2, b3;
            ldmx4(b0, b1, b2, b3,
                  Bbase + (uint32_t)(((wn * 64 + ntp * 16) * GSTR + ks * 16) * 2));
            uint32_t blo[2] = {b0, b1};
            uint32_t bhi[2] = {b2, b3};
#pragma unroll
            for (int mt = 0; mt < 2; mt++) {
                mma_f16(c[mt][2 * ntp],     a[mt], blo);
                mma_f16(c[mt][2 * ntp + 1], a[mt], bhi);
            }
        }
    }
}

// ---------------------------------------------------------------------------
// Merged Q/K/V projection GEMM: reads fp32 inputs/weights directly, converts
// in-register, writes fp16 head-split (b,h,n,d). Grid (8, 160).
// ---------------------------------------------------------------------------
__global__ __launch_bounds__(256, 2)
void gemm_qkv(const float* __restrict__ Xq, const float* __restrict__ Wq,
              const float* __restrict__ bq, __half* __restrict__ Oq,
              const float* __restrict__ Xk, const float* __restrict__ Wk,
              const float* __restrict__ bk, __half* __restrict__ Ok,
              const float* __restrict__ Xv, const float* __restrict__ Wv,
              const float* __restrict__ bv, __half* __restrict__ Ov)
{
    extern __shared__ __half smh[];   // 2 stages x 2 tensors x GSTG halves

    const int by = blockIdx.y;
    const float *A, *W, *bias;
    __half* out;
    int nP, rb;
    if (by < 32)      { A = Xq; W = Wq; bias = bq; out = Oq; nP = NQ; rb = by; }
    else if (by < 96) { A = Xk; W = Wk; bias = bk; out = Ok; nP = NK; rb = by - 32; }
    else              { A = Xv; W = Wv; bias = bv; out = Ov; nP = NK; rb = by - 96; }

    const int tid = threadIdx.x;
    const int wid = tid >> 5;
    const int lane = tid & 31;
    const int g = lane >> 2;
    const int tq = lane & 3;
    const int wm = wid & 3;
    const int wn = wid >> 2;
    const int row0 = rb * 128;
    const int col0 = blockIdx.x * 128;

    const float* Asrc = A + (size_t)row0 * EMBED;
    const float* Wsrc = W + (size_t)col0 * EMBED;

    const uint32_t aoff = (uint32_t)((((lane & 7) + ((lane >> 3) & 1) * 8) * GSTR
                                      + ((lane >> 4) & 1) * 8) * 2);
    const uint32_t boff = (uint32_t)((((lane & 7) + ((lane >> 4) & 1) * 8) * GSTR
                                      + ((lane >> 3) & 1) * 8) * 2);

    float c[2][8][4];
#pragma unroll
    for (int mt = 0; mt < 2; mt++)
#pragma unroll
        for (int nt = 0; nt < 8; nt++)
#pragma unroll
            for (int i = 0; i < 4; i++) c[mt][nt][i] = 0.f;

    stage_f32tile(smh,        Asrc, tid);
    stage_f32tile(smh + GSTG, Wsrc, tid);
    __syncthreads();

    for (int it = 0; it < 16; it++) {
        const __half* As = smh + (it & 1) * 2 * GSTG;
        compute_iter(As, wm, wn, aoff, boff, c);
        if (it < 15) {
            __half* Ds = smh + ((it + 1) & 1) * 2 * GSTG;
            stage_f32tile(Ds,        Asrc + (it + 1) * 64, tid);
            stage_f32tile(Ds + GSTG, Wsrc + (it + 1) * 64, tid);
        }
        __syncthreads();
    }

    // epilogue: fp16 head-split
#pragma unroll
    for (int mt = 0; mt < 2; mt++) {
#pragma unroll
        for (int half_ = 0; half_ < 2; half_++) {
            int grow = row0 + wm * 32 + mt * 16 + g + half_ * 8;
            int bb = grow / nP, n = grow - bb * nP;
#pragma unroll
            for (int nt = 0; nt < 8; nt++) {
                int gcol = col0 + wn * 64 + nt * 8 + tq * 2;
                float v0 = c[mt][nt][half_ * 2 + 0] + bias[gcol];
                float v1 = c[mt][nt][half_ * 2 + 1] + bias[gcol + 1];
                int h = gcol >> 6, d = gcol & 63;
                uint32_t* op = (uint32_t*)(out +
                    (((size_t)bb * HEADS + h) * nP + n) * HDIM + d);
                *op = packh2(v0, v1);
            }
        }
    }
}

// ---------------------------------------------------------------------------
// Output projection: A fp16 (attn result), W fp32 converted in-register,
// fp32 plain output. Grid (8, 32).
// ---------------------------------------------------------------------------
__global__ __launch_bounds__(256, 2)
void gemm_o(const __half* __restrict__ A, const float* __restrict__ W,
            const float* __restrict__ bias, float* __restrict__ out)
{
    extern __shared__ __half smh[];

    const int tid = threadIdx.x;
    const int wid = tid >> 5;
    const int lane = tid & 31;
    const int g = lane >> 2;
    const int tq = lane & 3;
    const int wm = wid & 3;
    const int wn = wid >> 2;
    const int row0 = blockIdx.y * 128;
    const int col0 = blockIdx.x * 128;

    const __half* Asrc = A + (size_t)row0 * EMBED;
    const float* Wsrc = W + (size_t)col0 * EMBED;

    const uint32_t aoff = (uint32_t)((((lane & 7) + ((lane >> 3) & 1) * 8) * GSTR
                                      + ((lane >> 4) & 1) * 8) * 2);
    const uint32_t boff = (uint32_t)((((lane & 7) + ((lane >> 4) & 1) * 8) * GSTR
                                      + ((lane >> 3) & 1) * 8) * 2);

    float c[2][8][4];
#pragma unroll
    for (int mt = 0; mt < 2; mt++)
#pragma unroll
        for (int nt = 0; nt < 8; nt++)
#pragma unroll
            for (int i = 0; i < 4; i++) c[mt][nt][i] = 0.f;

    stage_f16tile(smh,        Asrc, tid);
    stage_f32tile(smh + GSTG, Wsrc, tid);
    __syncthreads();

    for (int it = 0; it < 16; it++) {
        const __half* As = smh + (it & 1) * 2 * GSTG;
        compute_iter(As, wm, wn, aoff, boff, c);
        if (it < 15) {
            __half* Ds = smh + ((it + 1) & 1) * 2 * GSTG;
            stage_f16tile(Ds,        Asrc + (it + 1) * 64, tid);
            stage_f32tile(Ds + GSTG, Wsrc + (it + 1) * 64, tid);
        }
        __syncthreads();
    }

#pragma unroll
    for (int mt = 0; mt < 2; mt++) {
#pragma unroll
        for (int half_ = 0; half_ < 2; half_++) {
            int grow = row0 + wm * 32 + mt * 16 + g + half_ * 8;
#pragma unroll
            for (int nt = 0; nt < 8; nt++) {
                int gcol = col0 + wn * 64 + nt * 8 + tq * 2;
                float v0 = c[mt][nt][half_ * 2 + 0] + bias[gcol];
                float v1 = c[mt][nt][half_ * 2 + 1] + bias[gcol + 1];
                *(float2*)(out + (size_t)grow * EMBED + gcol) = make_float2(v0, v1);
            }
        }
    }
}

// ---------------------------------------------------------------------------
// Attention, fp16 mma + ldmatrix, 3-stage cp.async K/V pipeline.
// CTA: 128 q (8 warps x 16q), 64-key chunks.
// ---------------------------------------------------------------------------
#define ASTR 72
#define Q_HALVES (128 * ASTR)
#define KV_HALVES (64 * ASTR)

__global__ __launch_bounds__(256, 2)
void attn5(const __half* __restrict__ Q, const __half* __restrict__ K,
           const __half* __restrict__ V, const float* __restrict__ mult,
           __half* __restrict__ Out)
{
    extern __shared__ __half sh[];
    __half* Qs = sh;

    const int tid  = threadIdx.x;
    const int w    = tid >> 5;
    const int lane = tid & 31;
    const int g    = lane >> 2;
    const int tq   = lane & 3;
    const int bx = blockIdx.x;
    const int q0 = (bx & 7) * 128;
    const int h  = (bx >> 3) & 15;
    const int b  = bx >> 7;

    const __half* Qbase = Q + (((size_t)(b * HEADS + h) * NQ) + q0) * HDIM;
    const __half* Kbase = K + ((size_t)(b * HEADS + h) * NK) * HDIM;
    const __half* Vbase = V + ((size_t)(b * HEADS + h) * NK) * HDIM;
    const float* mbase = mult + (size_t)b * NK;

#pragma unroll
    for (int i = 0; i < 4; i++) {
        int f = tid + i * 256;
        int r = f >> 3, cc = f & 7;
        CP_ASYNC16(smem_u32(&Qs[r * ASTR + cc * 8]),
                   Qbase + (size_t)r * HDIM + cc * 8);
    }

    auto load_kv = [&](int s, int c0) {
        __half* Ks = sh + Q_HALVES + s * 2 * KV_HALVES;
        __half* Vs = Ks + KV_HALVES;
#pragma unroll
        for (int i = 0; i < 2; i++) {
            int f = tid + i * 256;
            int r = f >> 3, cc = f & 7;
            CP_ASYNC16(smem_u32(&Ks[r * ASTR + cc * 8]),
                       Kbase + (size_t)(c0 + r) * HDIM + cc * 8);
            CP_ASYNC16(smem_u32(&Vs[r * ASTR + cc * 8]),
                       Vbase + (size_t)(c0 + r) * HDIM + cc * 8);
        }
    };

    load_kv(0, 0);  CP_COMMIT();
    load_kv(1, 64); CP_COMMIT();

    const int qb = w * 16;
    const uint32_t aoff = (uint32_t)((((lane & 7) + ((lane >> 3) & 1) * 8) * ASTR
                                      + ((lane >> 4) & 1) * 8) * 2);
    const uint32_t boff = (uint32_t)((((lane & 7) + ((lane >> 4) & 1) * 8) * ASTR
                                      + ((lane >> 3) & 1) * 8) * 2);
    const int mi = lane >> 3, rl = lane & 7;
    const uint32_t vlane_off = (uint32_t)((rl + 8 * (mi & 1)) * ASTR + 8 * (mi >> 1));

    float m0 = -INFINITY, m1 = -INFINITY, l0 = 0.f, l1 = 0.f;
    float Oc[8][4];
#pragma unroll
    for (int dt = 0; dt < 8; dt++)
#pragma unroll
        for (int i = 0; i < 4; i++) Oc[dt][i] = 0.f;

    const uint32_t Qsb = smem_u32(Qs) + aoff + (uint32_t)(qb * ASTR * 2);

    for (int cidx = 0; cidx < 32; cidx++) {
        const int c0 = cidx * 64;
        float2 mv = *(const float2*)(mbase + c0 + 2 * lane);
        float lm0 = __logf(mv.x);
        float lm1 = __logf(mv.y);

        CP_WAIT1();
        __syncthreads();
        if (cidx + 2 < 32) load_kv((cidx + 2) % 3, c0 + 128);
        CP_COMMIT();

        const __half* Ksh = sh + Q_HALVES + (cidx % 3) * 2 * KV_HALVES;
        const uint32_t Kb = smem_u32(Ksh) + boff;
        const uint32_t vbase = smem_u32(Ksh + KV_HALVES) + vlane_off * 2;

        // ---- S = Q K^T ----
        float Sc[8][4];
#pragma unroll
        for (int nt = 0; nt < 8; nt++)
#pragma unroll
            for (int i = 0; i < 4; i++) Sc[nt][i] = 0.f;

#pragma unroll
        for (int ks = 0; ks < 4; ks++) {
            uint32_t a[4];
            ldmx4(a[0], a[1], a[2], a[3], Qsb + (uint32_t)(ks * 32));
#pragma unroll
            for (int ntp = 0; ntp < 4; ntp++) {
                uint32_t b0, b1, b2, b3;
                ldmx4(b0, b1, b2, b3,
                      Kb + (uint32_t)((ntp * 16 * ASTR + ks * 16) * 2));
                uint32_t blo[2] = {b0, b1};
                uint32_t bhi[2] = {b2, b3};
                mma_f16(Sc[2 * ntp], a, blo);
                mma_f16(Sc[2 * ntp + 1], a, bhi);
            }
        }

        // ---- softmax ----
        float rmax0 = -INFINITY, rmax1 = -INFINITY;
#pragma unroll
        for (int nt = 0; nt < 8; nt++) {
            float lmA = __shfl_sync(0xffffffffu, lm0, nt * 4 + tq);
            float lmB = __shfl_sync(0xffffffffu, lm1, nt * 4 + tq);
            Sc[nt][0] = Sc[nt][0] * 0.125f + lmA;
            Sc[nt][1] = Sc[nt][1] * 0.125f + lmB;
            Sc[nt][2] = Sc[nt][2] * 0.125f + lmA;
            Sc[nt][3] = Sc[nt][3] * 0.125f + lmB;
            rmax0 = fmaxf(rmax0, fmaxf(Sc[nt][0], Sc[nt][1]));
            rmax1 = fmaxf(rmax1, fmaxf(Sc[nt][2], Sc[nt][3]));
        }
        rmax0 = fmaxf(rmax0, __shfl_xor_sync(0xffffffffu, rmax0, 1));
        rmax0 = fmaxf(rmax0, __shfl_xor_sync(0xffffffffu, rmax0, 2));
        rmax1 = fmaxf(rmax1, __shfl_xor_sync(0xffffffffu, rmax1, 1));
        rmax1 = fmaxf(rmax1, __shfl_xor_sync(0xffffffffu, rmax1, 2));

        float mn0 = fmaxf(m0, rmax0);
        float mn1 = fmaxf(m1, rmax1);
        float alpha0 = __expf(m0 - mn0);
        float alpha1 = __expf(m1 - mn1);
        m0 = mn0; m1 = mn1;

        float ls0 = 0.f, ls1 = 0.f;
#pragma unroll
        for (int nt = 0; nt < 8; nt++) {
            Sc[nt][0] = __expf(Sc[nt][0] - mn0);
            Sc[nt][1] = __expf(Sc[nt][1] - mn0);
            Sc[nt][2] = __expf(Sc[nt][2] - mn1);
            Sc[nt][3] = __expf(Sc[nt][3] - mn1);
            ls0 += Sc[nt][0] + Sc[nt][1];
            ls1 += Sc[nt][2] + Sc[nt][3];
        }
        ls0 += __shfl_xor_sync(0xffffffffu, ls0, 1);
        ls0 += __shfl_xor_sync(0xffffffffu, ls0, 2);
        ls1 += __shfl_xor_sync(0xffffffffu, ls1, 1);
        ls1 += __shfl_xor_sync(0xffffffffu, ls1, 2);
        l0 = l0 * alpha0 + ls0;
        l1 = l1 * alpha1 + ls1;

#pragma unroll
        for (int dt = 0; dt < 8; dt++) {
            Oc[dt][0] *= alpha0; Oc[dt][1] *= alpha0;
            Oc[dt][2] *= alpha1; Oc[dt][3] *= alpha1;
        }

        // ---- P C-frags -> fp16 A-frags ----
        uint32_t Pa[4][4];
#pragma unroll
        for (int j = 0; j < 4; j++) {
            Pa[j][0] = packh2(Sc[2 * j][0],     Sc[2 * j][1]);
            Pa[j][1] = packh2(Sc[2 * j][2],     Sc[2 * j][3]);
            Pa[j][2] = packh2(Sc[2 * j + 1][0], Sc[2 * j + 1][1]);
            Pa[j][3] = packh2(Sc[2 * j + 1][2], Sc[2 * j + 1][3]);
        }

        // ---- O += P V ----
#pragma unroll
        for (int j = 0; j < 4; j++) {
            const uint32_t abase = vbase + j * (16 * ASTR * 2);
#pragma unroll
            for (int dtp = 0; dtp < 4; dtp++) {
                uint32_t r0, r1, r2, r3;
                ldmx4_trans(r0, r1, r2, r3, abase + dtp * 32);
                uint32_t blo[2] = {r0, r1};
                uint32_t bhi[2] = {r2, r3};
                mma_f16(Oc[2 * dtp],     Pa[j], blo);
                mma_f16(Oc[2 * dtp + 1], Pa[j], bhi);
            }
        }
    }

    // ---- write out fp16 ----
    const float inv0 = 1.f / l0;
    const float inv1 = 1.f / l1;
    const int qg0 = q0 + qb + g;
    __half* o0 = Out + ((size_t)(b * NQ + qg0)) * EMBED + h * HDIM;
    __half* o1 = o0 + (size_t)8 * EMBED;
#pragma unroll
    for (int dt = 0; dt < 8; dt++) {
        int col = dt * 8 + 2 * tq;
        *(uint32_t*)(o0 + col) = packh2(Oc[dt][0] * inv0, Oc[dt][1] * inv0);
        *(uint32_t*)(o1 + col) = packh2(Oc[dt][2] * inv1, Oc[dt][3] * inv1);
    }
}

// ---------------------------------------------------------------------------
// launch — 3 kernels total, no prepass
// ---------------------------------------------------------------------------
extern "C" void kernel_launch(void* const* d_in, const int* in_sizes, int n_in,
                              void* d_out, int out_size)
{
    const float* query = (const float*)d_in[0];
    const float* key   = (const float*)d_in[1];
    const float* value = (const float*)d_in[2];
    const float* mult  = (const float*)d_in[3];
    const float* wq_w  = (const float*)d_in[4];
    const float* wq_b  = (const float*)d_in[5];
    const float* wk_w  = (const float*)d_in[6];
    const float* wk_b  = (const float*)d_in[7];
    const float* wv_w  = (const float*)d_in[8];
    const float* wv_b  = (const float*)d_in[9];
    const float* wo_w  = (const float*)d_in[10];
    const float* wo_b  = (const float*)d_in[11];
    float* out = (float*)d_out;

    __half *gQ, *gK, *gV, *gA;
    cudaGetSymbolAddress((void**)&gQ, g_Q);
    cudaGetSymbolAddress((void**)&gK, g_K);
    cudaGetSymbolAddress((void**)&gV, g_V);
    cudaGetSymbolAddress((void**)&gA, g_A);

    const int GEMM_SMEM = 2 * 2 * GSTG * 2;                    // 73728
    const int ATTN_SMEM = (Q_HALVES + 3 * 2 * KV_HALVES) * 2;  // 73728
    cudaFuncSetAttribute(gemm_qkv, cudaFuncAttributeMaxDynamicSharedMemorySize, GEMM_SMEM);
    cudaFuncSetAttribute(gemm_o,   cudaFuncAttributeMaxDynamicSharedMemorySize, GEMM_SMEM);
    cudaFuncSetAttribute(attn5, cudaFuncAttributeMaxDynamicSharedMemorySize, ATTN_SMEM);

    dim3 blk(256);
    // merged Q/K/V projections, fp32 -> fp16 conversion fused in
    gemm_qkv<<<dim3(8, 160), blk, GEMM_SMEM>>>(query, wq_w, wq_b, gQ,
                                               key,   wk_w, wk_b, gK,
                                               value, wv_w, wv_b, gV);

    // attention
    attn5<<<BATCH * HEADS * (NQ / 128), blk, ATTN_SMEM>>>(gQ, gK, gV, mult, gA);

    // output projection
    gemm_o<<<dim3(8, 32), blk, GEMM_SMEM>>>(gA, wo_w, wo_b, out);
}